// round 10
// baseline (speedup 1.0000x reference)
#include <cuda_runtime.h>

// Problem: x[32,64,32,32] f32, gamma/beta [16,64], out [32, 16*64, 32, 32] f32
#define B_       32
#define C_       64
#define HW4_     256                 // 32*32 in float4 units
#define N_       16
#define NPLANES_ (B_ * C_)           // 2048
#define GRID_    296                 // 2 blocks per SM on 148 SMs (full wave 1)
#define INV_CNT  (1.0f / 32768.0f)   // 1/(B*H*W)

// Scratch (static device globals; no allocation)
__device__ float    g_psum[NPLANES_];
__device__ float    g_psq [NPLANES_];
__device__ float    g_sg  [N_ * C_];
__device__ float    g_sb  [N_ * C_];
__device__ unsigned g_count = 0;
__device__ volatile unsigned g_gate = 0;

// ---------------------------------------------------------------------------
// One persistent kernel: reduce -> device-wide gate (last block finalizes)
// -> apply. Grid is exactly wave-1 resident, so the gate spin cannot deadlock.
// ---------------------------------------------------------------------------
__global__ void __launch_bounds__(256, 2)
fused_bn_kernel(const float4* __restrict__ x4,
                const float*  __restrict__ gamma,
                const float*  __restrict__ beta,
                float4*       __restrict__ out4)
{
    const int t    = threadIdx.x;
    const int lane = t & 31;
    const int w    = t >> 5;

    __shared__ unsigned s_last;
    __shared__ float m_s[C_], i_s[C_];

    // Every block reads the gate BEFORE any sync work; the gate can only
    // advance after all 296 blocks have passed phase 1, i.e. after this read.
    const unsigned start_gate = g_gate;

    // ---------------- Phase 1: per-plane partial sums (1 warp = 1 plane) ----
    const int gw = blockIdx.x * 8 + w;          // global warp id, 0..2367
    if (gw < NPLANES_) {
        const float4* p = x4 + gw * HW4_;
        float s = 0.f, q = 0.f;
        #pragma unroll
        for (int i = 0; i < 8; i++) {           // MLP=8, fully coalesced
            const float4 v = __ldg(&p[i * 32 + lane]);
            s += v.x + v.y + v.z + v.w;
            q += v.x*v.x + v.y*v.y + v.z*v.z + v.w*v.w;
        }
        #pragma unroll
        for (int o = 16; o > 0; o >>= 1) {
            s += __shfl_down_sync(0xFFFFFFFFu, s, o);
            q += __shfl_down_sync(0xFFFFFFFFu, q, o);
        }
        if (lane == 0) { g_psum[gw] = s; g_psq[gw] = q; }
    }

    // ---------------- Device-wide gate ----------------
    __syncthreads();
    if (t == 0) {
        __threadfence();                         // publish this block's partials
        const unsigned old = atomicAdd(&g_count, 1u);
        s_last = (old == GRID_ - 1u);
    }
    __syncthreads();

    if (s_last) {
        // Last block: all 2048 partials are published. Finalize fold params.
        __threadfence();
        if (t < C_) {
            float s = 0.f, q = 0.f;
            #pragma unroll 8
            for (int b = 0; b < B_; b++) {
                s += g_psum[b * C_ + t];
                q += g_psq [b * C_ + t];
            }
            const float mean = s * INV_CNT;
            const float var  = fmaf(-mean, mean, q * INV_CNT);  // biased var
            m_s[t] = mean;
            i_s[t] = rsqrtf(var + 1e-5f);
        }
        __syncthreads();
        #pragma unroll
        for (int k = 0; k < 4; k++) {
            const int idx = k * 256 + t;         // linear over [N,C]
            const int c   = idx & (C_ - 1);
            const float sg = gamma[idx] * i_s[c];
            g_sg[idx] = sg;
            g_sb[idx] = fmaf(-sg, m_s[c], beta[idx]);
        }
        __threadfence();                         // publish sg/sb
        __syncthreads();
        if (t == 0) {
            g_count = 0;                         // reset for next graph replay
            __threadfence();
            g_gate = start_gate + 1u;            // open the gate
        }
    } else {
        if (t == 0) {
            while (g_gate == start_gate) __nanosleep(64);
            __threadfence();
        }
        __syncthreads();
    }

    // ---------------- Phase 3: apply (strided planes, no barriers) ----------
    for (int p = blockIdx.x; p < NPLANES_; p += GRID_) {
        const int b = p >> 6;
        const int c = p & (C_ - 1);

        const float4 v = __ldg(&x4[p * HW4_ + t]);   // L2-resident from phase 1

        // Per-warp param fetch: lanes 0..15 hold sg[n], lanes 16..31 hold sb[n]
        const int   nn = lane & 15;
        const float f  = (lane < 16) ? __ldg(&g_sg[nn * C_ + c])
                                     : __ldg(&g_sb[nn * C_ + c]);

        const int obase = b * (N_ * C_ * HW4_) + c * HW4_ + t;

        #pragma unroll
        for (int n = 0; n < N_; n++) {
            const float s  = __shfl_sync(0xFFFFFFFFu, f, n);
            const float tb = __shfl_sync(0xFFFFFFFFu, f, n + 16);
            float4 o;
            o.x = fmaf(s, v.x, tb);
            o.y = fmaf(s, v.y, tb);
            o.z = fmaf(s, v.z, tb);
            o.w = fmaf(s, v.w, tb);
            __stcs(&out4[obase + n * (C_ * HW4_)], o);   // evict-first stream
        }
    }
}

// ---------------------------------------------------------------------------
extern "C" void kernel_launch(void* const* d_in, const int* in_sizes, int n_in,
                              void* d_out, int out_size) {
    const float4* x4    = (const float4*)d_in[0];  // x [32,64,32,32]
    const float*  gamma = (const float*) d_in[1];  // [16,64]
    const float*  beta  = (const float*) d_in[2];  // [16,64]
    float4*       out4  = (float4*)d_out;          // [32,1024,32,32]

    fused_bn_kernel<<<GRID_, 256>>>(x4, gamma, beta, out4);
}

// round 11
// speedup vs baseline: 1.0010x; 1.0010x over previous
#include <cuda_runtime.h>

// Problem: x[32,64,32,32] f32, gamma/beta [16,64], out [32, 16*64, 32, 32] f32
#define B_       32
#define C_       64
#define HW4_     256                 // 32*32 in float4 units
#define N_       16
#define NPLANES_ (B_ * C_)           // 2048
#define GRID_    296                 // 2 blocks per SM on 148 SMs (full wave 1)
#define INV_CNT  (1.0f / 32768.0f)   // 1/(B*H*W)

// Scratch (static device globals; no allocation)
__device__ float    g_psum[NPLANES_];
__device__ float    g_psq [NPLANES_];
__device__ float    g_sg  [N_ * C_];
__device__ float    g_sb  [N_ * C_];
__device__ unsigned g_count = 0;
__device__ volatile unsigned g_gate = 0;

// ---------------------------------------------------------------------------
// One persistent kernel: reduce -> device-wide gate (last block finalizes)
// -> apply. Grid is exactly wave-1 resident, so the gate spin cannot deadlock.
// ---------------------------------------------------------------------------
__global__ void __launch_bounds__(256, 2)
fused_bn_kernel(const float4* __restrict__ x4,
                const float*  __restrict__ gamma,
                const float*  __restrict__ beta,
                float4*       __restrict__ out4)
{
    const int t    = threadIdx.x;
    const int lane = t & 31;
    const int w    = t >> 5;

    __shared__ unsigned s_last;
    __shared__ float m_s[C_], i_s[C_];

    // Every block reads the gate BEFORE any sync work; the gate can only
    // advance after all 296 blocks have passed phase 1, i.e. after this read.
    const unsigned start_gate = g_gate;

    // ---------------- Phase 1: per-plane partial sums (1 warp = 1 plane) ----
    const int gw = blockIdx.x * 8 + w;          // global warp id, 0..2367
    if (gw < NPLANES_) {
        const float4* p = x4 + gw * HW4_;
        float s = 0.f, q = 0.f;
        #pragma unroll
        for (int i = 0; i < 8; i++) {           // MLP=8, fully coalesced
            const float4 v = __ldg(&p[i * 32 + lane]);
            s += v.x + v.y + v.z + v.w;
            q += v.x*v.x + v.y*v.y + v.z*v.z + v.w*v.w;
        }
        #pragma unroll
        for (int o = 16; o > 0; o >>= 1) {
            s += __shfl_down_sync(0xFFFFFFFFu, s, o);
            q += __shfl_down_sync(0xFFFFFFFFu, q, o);
        }
        if (lane == 0) { g_psum[gw] = s; g_psq[gw] = q; }
    }

    // ---------------- Device-wide gate ----------------
    __syncthreads();
    if (t == 0) {
        __threadfence();                         // publish this block's partials
        const unsigned old = atomicAdd(&g_count, 1u);
        s_last = (old == GRID_ - 1u);
    }
    __syncthreads();

    if (s_last) {
        // Last block: all 2048 partials are published. Finalize fold params.
        __threadfence();
        if (t < C_) {
            float s = 0.f, q = 0.f;
            #pragma unroll 8
            for (int b = 0; b < B_; b++) {
                s += g_psum[b * C_ + t];
                q += g_psq [b * C_ + t];
            }
            const float mean = s * INV_CNT;
            const float var  = fmaf(-mean, mean, q * INV_CNT);  // biased var
            m_s[t] = mean;
            i_s[t] = rsqrtf(var + 1e-5f);
        }
        __syncthreads();
        #pragma unroll
        for (int k = 0; k < 4; k++) {
            const int idx = k * 256 + t;         // linear over [N,C]
            const int c   = idx & (C_ - 1);
            const float sg = gamma[idx] * i_s[c];
            g_sg[idx] = sg;
            g_sb[idx] = fmaf(-sg, m_s[c], beta[idx]);
        }
        __threadfence();                         // publish sg/sb
        __syncthreads();
        if (t == 0) {
            g_count = 0;                         // reset for next graph replay
            __threadfence();
            g_gate = start_gate + 1u;            // open the gate
        }
    } else {
        if (t == 0) {
            while (g_gate == start_gate) __nanosleep(64);
            __threadfence();
        }
        __syncthreads();
    }

    // ---------------- Phase 3: apply (strided planes, no barriers) ----------
    for (int p = blockIdx.x; p < NPLANES_; p += GRID_) {
        const int b = p >> 6;
        const int c = p & (C_ - 1);

        const float4 v = __ldg(&x4[p * HW4_ + t]);   // L2-resident from phase 1

        // Per-warp param fetch: lanes 0..15 hold sg[n], lanes 16..31 hold sb[n]
        const int   nn = lane & 15;
        const float f  = (lane < 16) ? __ldg(&g_sg[nn * C_ + c])
                                     : __ldg(&g_sb[nn * C_ + c]);

        const int obase = b * (N_ * C_ * HW4_) + c * HW4_ + t;

        #pragma unroll
        for (int n = 0; n < N_; n++) {
            const float s  = __shfl_sync(0xFFFFFFFFu, f, n);
            const float tb = __shfl_sync(0xFFFFFFFFu, f, n + 16);
            float4 o;
            o.x = fmaf(s, v.x, tb);
            o.y = fmaf(s, v.y, tb);
            o.z = fmaf(s, v.z, tb);
            o.w = fmaf(s, v.w, tb);
            __stcs(&out4[obase + n * (C_ * HW4_)], o);   // evict-first stream
        }
    }
}

// ---------------------------------------------------------------------------
extern "C" void kernel_launch(void* const* d_in, const int* in_sizes, int n_in,
                              void* d_out, int out_size) {
    const float4* x4    = (const float4*)d_in[0];  // x [32,64,32,32]
    const float*  gamma = (const float*) d_in[1];  // [16,64]
    const float*  beta  = (const float*) d_in[2];  // [16,64]
    float4*       out4  = (float4*)d_out;          // [32,1024,32,32]

    fused_bn_kernel<<<GRID_, 256>>>(x4, gamma, beta, out4);
}

// round 12
// speedup vs baseline: 1.1511x; 1.1499x over previous
#include <cuda_runtime.h>

// Problem: x[32,64,32,32] f32, gamma/beta [16,64], out [32, 16*64, 32, 32] f32
#define B_       32
#define C_       64
#define HW4_     256                 // 32*32 in float4 units
#define N_       16
#define NPLANES_ (B_ * C_)           // 2048
#define GRP_     4                   // batch groups in reduce
#define BPG_     (B_ / GRP_)         // 8 batches per group
#define INV_CNT  (1.0f / 32768.0f)   // 1/(B*H*W)

// Scratch (static device globals; no allocation). Layout: [g*C + c]
__device__ float g_psum[GRP_ * C_];
__device__ float g_psq [GRP_ * C_];

// ---------------------------------------------------------------------------
// Kernel 1: partial sums. 256 blocks = (g in 0..3) x (c in 0..63).
// Each block covers 8 full (b,c) planes of one channel: 256 threads x
// 8 independent float4 loads (MLP=8) -> latency hidden.
// ---------------------------------------------------------------------------
__global__ __launch_bounds__(256) void reduce_kernel(const float4* __restrict__ x4) {
    const int c = blockIdx.x & (C_ - 1);
    const int g = blockIdx.x >> 6;           // 0..3
    const int t = threadIdx.x;               // 0..255 -> one float4 per plane

    float s = 0.f, q = 0.f;
    #pragma unroll
    for (int j = 0; j < BPG_; j++) {
        const int b = g * BPG_ + j;
        const float4 v = __ldg(&x4[(b * C_ + c) * HW4_ + t]);  // coalesced
        s += v.x + v.y + v.z + v.w;
        q += v.x*v.x + v.y*v.y + v.z*v.z + v.w*v.w;
    }

    #pragma unroll
    for (int o = 16; o > 0; o >>= 1) {
        s += __shfl_down_sync(0xFFFFFFFFu, s, o);
        q += __shfl_down_sync(0xFFFFFFFFu, q, o);
    }
    __shared__ float ss[8], qq[8];
    const int w = t >> 5;
    if ((t & 31) == 0) { ss[w] = s; qq[w] = q; }
    __syncthreads();
    if (t == 0) {
        float S = 0.f, Q = 0.f;
        #pragma unroll
        for (int i = 0; i < 8; i++) { S += ss[i]; Q += qq[i]; }
        g_psum[blockIdx.x] = S;   // blockIdx.x == g*C + c
        g_psq [blockIdx.x] = Q;
    }
}

// ---------------------------------------------------------------------------
// Kernel 2: apply, barrier-free. One block per (b,c) plane; each WARP
// independently finalizes the channel stats from the 8 group partials
// (L2-hit loads + shuffles, overlapped with the x-plane load latency),
// holds sg/sb for the 16 branches in lane registers, then streams 16
// FMA'd float4 __stcs stores per thread. No __syncthreads, no smem.
// ---------------------------------------------------------------------------
__global__ __launch_bounds__(256) void apply_kernel(const float4* __restrict__ x4,
                                                    const float* __restrict__ gamma,
                                                    const float* __restrict__ beta,
                                                    float4* __restrict__ out4) {
    const int bc   = blockIdx.x;         // b*C + c
    const int c    = bc & (C_ - 1);
    const int b    = bc >> 6;
    const int t    = threadIdx.x;        // 0..255
    const int lane = t & 31;

    // Issue the big global load FIRST; everything below is independent of it.
    const float4 v = __ldg(&x4[bc * HW4_ + t]);

    // --- per-warp finalize (redundant across warps, but barrier-free) ---
    // lanes 0..3 load psum[g][c], lanes 4..7 load psq[g][c]; butterfly-sum
    // within each group of 4 lanes.
    float pv = 0.f;
    if (lane < 8) {
        pv = (lane < 4) ? __ldg(&g_psum[lane * C_ + c])
                        : __ldg(&g_psq [(lane - 4) * C_ + c]);
    }
    pv += __shfl_xor_sync(0xFFFFFFFFu, pv, 1);
    pv += __shfl_xor_sync(0xFFFFFFFFu, pv, 2);
    const float s   = __shfl_sync(0xFFFFFFFFu, pv, 0);   // total sum
    const float q   = __shfl_sync(0xFFFFFFFFu, pv, 4);   // total sumsq
    const float mean = s * INV_CNT;
    const float var  = fmaf(-mean, mean, q * INV_CNT);   // biased var
    const float inv  = rsqrtf(var + 1e-5f);

    // lanes 0..15 own branch n = lane: fold gamma/beta into (sgv, sbv)
    float sgv = 0.f, sbv = 0.f;
    if (lane < N_) {
        const float ga = __ldg(&gamma[lane * C_ + c]);   // L2-resident (256 addrs)
        const float be = __ldg(&beta [lane * C_ + c]);
        sgv = ga * inv;
        sbv = fmaf(-sgv, mean, be);
    }

    // out linear (float4 units): (b*(N*C) + n*C + c) * HW4 + t
    const int obase = (b * (N_ * C_) + c) * HW4_ + t;

    #pragma unroll
    for (int n = 0; n < N_; n++) {
        const float sc = __shfl_sync(0xFFFFFFFFu, sgv, n);
        const float tb = __shfl_sync(0xFFFFFFFFu, sbv, n);
        float4 o;
        o.x = fmaf(sc, v.x, tb);
        o.y = fmaf(sc, v.y, tb);
        o.z = fmaf(sc, v.z, tb);
        o.w = fmaf(sc, v.w, tb);
        __stcs(&out4[obase + n * (C_ * HW4_)], o);       // evict-first stream
    }
}

// ---------------------------------------------------------------------------
extern "C" void kernel_launch(void* const* d_in, const int* in_sizes, int n_in,
                              void* d_out, int out_size) {
    const float4* x4    = (const float4*)d_in[0];  // x [32,64,32,32]
    const float*  gamma = (const float*) d_in[1];  // [16,64]
    const float*  beta  = (const float*) d_in[2];  // [16,64]
    float4*       out4  = (float4*)d_out;          // [32,1024,32,32]

    reduce_kernel<<<GRP_ * C_, 256>>>(x4);
    apply_kernel <<<NPLANES_, 256>>>(x4, gamma, beta, out4);
}